// round 5
// baseline (speedup 1.0000x reference)
#include <cuda_runtime.h>

// Problem constants
#define BB 32
#define CC 256
#define HH 32
#define WW 32
#define NE 1024
#define NG 8
#define CPG 128   // codes per group
#define WPG 4     // w positions per group

#define ZQ_ELEMS  (BB*CC*HH*WW)          // 8388608
#define LOSS_OFF  (ZQ_ELEMS)             // loss, commitment, codebook
#define IDX_OFF   (ZQ_ELEMS + 3)         // 32768 indices as float
#define MEAN_DEN  ((double)ZQ_ELEMS)

#define CB_STRIDE 130                    // cbs_pair row stride in floats (65 float2)
#define ZD_STRIDE 66                     // zs_dup row stride in floats (33 float2)

__device__ float  g_codebook[NE*CC];
__device__ float  g_cnorm[NE];
__device__ double g_sqsum;

typedef unsigned long long ull;

__device__ __forceinline__ void ffma2(ull& acc, ull a, ull b) {
    asm("fma.rn.f32x2 %0, %1, %2, %0;" : "+l"(acc) : "l"(a), "l"(b));
}
__device__ __forceinline__ float lo32(ull v) { return __uint_as_float((unsigned)v); }
__device__ __forceinline__ float hi32(ull v) { return __uint_as_float((unsigned)(v >> 32)); }

// ---------------------------------------------------------------------------
// Kernel 1: codebook = emb @ proj^T (sequential ascending-k fma chain per
// element — bit-exact requirement), code norms, zero the loss accumulator.
// Grid: 256 blocks x 256 threads, each block does 4 codebook rows.
// ---------------------------------------------------------------------------
__global__ __launch_bounds__(256)
void prep_kernel(const float* __restrict__ emb,
                 const float* __restrict__ proj) {
    __shared__ float es[4*CC];
    __shared__ float part[4][9];         // [j][warp]
    int tid  = threadIdx.x;
    int lane = tid & 31;
    int warp = tid >> 5;
    int j0   = blockIdx.x * 4;

    for (int i = tid; i < 4*CC; i += 256) es[i] = emb[j0*CC + i];
    __syncthreads();

    int i = tid;          // output column
    float acc[4];
    #pragma unroll
    for (int j = 0; j < 4; j++) acc[j] = 0.f;

    const float4* pv = (const float4*)(proj + (size_t)i*CC);
    #pragma unroll 4
    for (int k4 = 0; k4 < CC/4; k4++) {
        float4 p = pv[k4];
        int k = k4*4;
        #pragma unroll
        for (int j = 0; j < 4; j++) acc[j] = fmaf(es[j*CC + k+0], p.x, acc[j]);
        #pragma unroll
        for (int j = 0; j < 4; j++) acc[j] = fmaf(es[j*CC + k+1], p.y, acc[j]);
        #pragma unroll
        for (int j = 0; j < 4; j++) acc[j] = fmaf(es[j*CC + k+2], p.z, acc[j]);
        #pragma unroll
        for (int j = 0; j < 4; j++) acc[j] = fmaf(es[j*CC + k+3], p.w, acc[j]);
    }
    #pragma unroll
    for (int j = 0; j < 4; j++)
        g_codebook[(size_t)(j0 + j)*CC + i] = acc[j];

    // code norms: order-insensitive at this magnitude -> shfl tree reduce
    #pragma unroll
    for (int j = 0; j < 4; j++) {
        float v = acc[j]*acc[j];
        #pragma unroll
        for (int off = 16; off; off >>= 1)
            v += __shfl_down_sync(0xffffffffu, v, off);
        if (lane == 0) part[j][warp] = v;
    }
    __syncthreads();
    if (tid < 4) {
        float s = 0.f;
        #pragma unroll
        for (int w = 0; w < 8; w++) s += part[tid][w];
        g_cnorm[j0 + tid] = s;
    }
    if (blockIdx.x == 0 && tid == 0) g_sqsum = 0.0;
}

// ---------------------------------------------------------------------------
// Kernel 2: main. Grid (16 chunks, 8 groups) x 512 threads (16 warps).
// smem: codebook in (j, j+64) float2 pairs [256 c][65 pairs]; z staged
// pre-duplicated {v,v} [256 c][33 pairs]; 256 tokens in 8 passes of 32.
// Per warp: 2 tokens, 4 codes/lane: inner iter = 4 LDS.64 + 4 FFMA2.
// ---------------------------------------------------------------------------
extern __shared__ float smem[];

__global__ __launch_bounds__(512, 1)
void main_kernel(const float* __restrict__ z, float* __restrict__ out) {
    float* cbp  = smem;                          // [256][65 float2] code pairs
    float* zdp  = cbp + CC*CB_STRIDE;            // [256][33 float2] dup'd z
    float* cn   = zdp + CC*ZD_STRIDE;            // [128]
    float* znorm_s = cn + CPG;                   // [32]
    __shared__ int    sel[32];
    __shared__ double wsum[16];

    int g     = blockIdx.y;
    int chunk = blockIdx.x;                      // 0..15
    int tid   = threadIdx.x;
    int lane  = tid & 31;
    int warp  = tid >> 5;                        // 0..15
    int w0    = g * WPG;

    // stage group codebook into pair layout: pair p at column c holds
    // (code p, code p+64).  Reads coalesced; one-time 2-way store conflicts.
    const float* cbg = g_codebook + (size_t)g*CPG*CC;
    for (int i = tid; i < CPG*CC; i += 512) {
        int j = i >> 8, c = i & 255;
        cbp[c*CB_STRIDE + ((j & 63) << 1) + (j >> 6)] = cbg[i];
    }
    if (tid < CPG) cn[tid] = g_cnorm[g*CPG + tid];
    __syncthreads();

    float lsum_f = 0.f;                          // fp32 loss accumulator

    int rl = warp >> 1;                          // row-in-pass 0..7
    int ch = warp & 1;                           // c-half

    for (int pass = 0; pass < 8; pass++) {
        int bh0 = chunk*64 + pass*8;             // 8 (b,h) rows per pass
        int bh  = bh0 + rl;
        int b = bh >> 5, h = bh & 31;
        const float4* src = (const float4*)(z + (size_t)b*262144 + (size_t)h*32 + w0);
        float4* dst = (float4*)(out + (size_t)b*262144 + (size_t)h*32 + w0);

        // ---- stage 32 tokens duplicated: zdp[c][tok] = {v, v} ----
        #pragma unroll
        for (int k = 0; k < 4; k++) {
            int c = ch*128 + lane + 32*k;
            float4 v = src[(size_t)c*256];       // z[b,c,h,w0..w0+3]
            float2* d = (float2*)(zdp + c*ZD_STRIDE + rl*8);
            d[0] = make_float2(v.x, v.x);
            d[1] = make_float2(v.y, v.y);
            d[2] = make_float2(v.z, v.z);
            d[3] = make_float2(v.w, v.w);
        }
        __syncthreads();

        // ---- znorm: reference-exact sequential chain, one thread/token ----
        if (tid < 32) {
            float acc = 0.f;
            #pragma unroll 8
            for (int c = 0; c < CC; c++) {
                float v = zdp[c*ZD_STRIDE + tid*2];
                acc = __fadd_rn(acc, __fmul_rn(v, v));
            }
            znorm_s[tid] = acc;
        }
        __syncthreads();

        // ---- dot products: warp owns tokens warp*2, warp*2+1 ----
        // each (code, token) half is a single sequential ascending-c fma
        // chain (bit-exact).  4 LDS.64 + 4 FFMA2 per c-iter.
        ull a00 = 0, a01 = 0, a10 = 0, a11 = 0;
        {
            const float* cb0 = cbp + lane*2;
            const float* zb  = zdp + warp*4;
            #pragma unroll 4
            for (int c = 0; c < CC; c++) {
                ull cp0 = *(const ull*)(cb0 + c*CB_STRIDE);        // codes (lane, lane+64)
                ull cp1 = *(const ull*)(cb0 + c*CB_STRIDE + 64);   // codes (lane+32, lane+96)
                ull zz0 = *(const ull*)(zb + c*ZD_STRIDE);         // token t0 dup'd
                ull zz1 = *(const ull*)(zb + c*ZD_STRIDE + 2);     // token t1 dup'd
                ffma2(a00, cp0, zz0); ffma2(a01, cp0, zz1);
                ffma2(a10, cp1, zz0); ffma2(a11, cp1, zz1);
            }
        }

        // ---- reference-exact distance + first-min argmin ----
        #pragma unroll
        for (int e = 0; e < 2; e++) {
            int t = warp*2 + e;
            float zn = znorm_s[t];
            ull axe = e ? a01 : a00;             // pair (lane, lane+64)
            ull bxe = e ? a11 : a10;             // pair (lane+32, lane+96)
            // candidates in ascending code index: lane, +32, +64, +96
            float dot0 = lo32(axe), dot1 = lo32(bxe);
            float dot2 = hi32(axe), dot3 = hi32(bxe);
            float best = __fsub_rn(__fadd_rn(zn, cn[lane]),    __fadd_rn(dot0, dot0));
            int   bj   = lane;
            float v1   = __fsub_rn(__fadd_rn(zn, cn[lane+32]), __fadd_rn(dot1, dot1));
            if (v1 < best) { best = v1; bj = lane+32; }
            float v2   = __fsub_rn(__fadd_rn(zn, cn[lane+64]), __fadd_rn(dot2, dot2));
            if (v2 < best) { best = v2; bj = lane+64; }
            float v3   = __fsub_rn(__fadd_rn(zn, cn[lane+96]), __fadd_rn(dot3, dot3));
            if (v3 < best) { best = v3; bj = lane+96; }
            #pragma unroll
            for (int off = 16; off; off >>= 1) {
                float ov = __shfl_down_sync(0xffffffffu, best, off);
                int   oj = __shfl_down_sync(0xffffffffu, bj,   off);
                if (ov < best || (ov == best && oj < bj)) { best = ov; bj = oj; }
            }
            if (lane == 0) sel[warp*2 + e] = bj;
        }
        __syncthreads();

        // ---- write zq (strided float4), accumulate (zq - z)^2 in fp32 ----
        {
            int s0 = sel[rl*4+0], s1 = sel[rl*4+1], s2 = sel[rl*4+2], s3 = sel[rl*4+3];
            int p0 = (s0 & 63)*2, h0 = s0 >> 6;
            int p1 = (s1 & 63)*2, h1 = s1 >> 6;
            int p2 = (s2 & 63)*2, h2 = s2 >> 6;
            int p3 = (s3 & 63)*2, h3 = s3 >> 6;
            #pragma unroll
            for (int k = 0; k < 4; k++) {
                int c = ch*128 + lane + 32*k;
                const float* row = cbp + c*CB_STRIDE;
                float2 q0 = *(const float2*)(row + p0);
                float2 q1 = *(const float2*)(row + p1);
                float2 q2 = *(const float2*)(row + p2);
                float2 q3 = *(const float2*)(row + p3);
                float4 v;
                v.x = h0 ? q0.y : q0.x;
                v.y = h1 ? q1.y : q1.x;
                v.z = h2 ? q2.y : q2.x;
                v.w = h3 ? q3.y : q3.x;
                dst[(size_t)c*256] = v;
                const float* zrow = zdp + c*ZD_STRIDE + rl*8;
                float d0 = v.x - zrow[0];
                float d1 = v.y - zrow[2];
                float d2 = v.z - zrow[4];
                float d3 = v.w - zrow[6];
                lsum_f = fmaf(d0, d0, lsum_f);
                lsum_f = fmaf(d1, d1, lsum_f);
                lsum_f = fmaf(d2, d2, lsum_f);
                lsum_f = fmaf(d3, d3, lsum_f);
            }
        }

        // ---- idx output (as float) ----
        if (tid < 32) {
            int bhi = bh0 + (tid >> 2);
            int wi  = tid & 3;
            int bb2 = bhi >> 5, hh2 = bhi & 31;
            out[IDX_OFF + bb2*1024 + hh2*32 + w0 + wi] = (float)(g*CPG + sel[tid]);
        }
        __syncthreads();   // protect zdp/sel reuse next pass
    }

    // block-reduce the squared-diff sum (double), one atomic per block
    double lsum = (double)lsum_f;
    #pragma unroll
    for (int off = 16; off; off >>= 1)
        lsum += __shfl_down_sync(0xffffffffu, lsum, off);
    if (lane == 0) wsum[warp] = lsum;
    __syncthreads();
    if (warp == 0) {
        double v = (lane < 16) ? wsum[lane] : 0.0;
        #pragma unroll
        for (int off = 8; off; off >>= 1)
            v += __shfl_down_sync(0xffffffffu, v, off);
        if (lane == 0) atomicAdd(&g_sqsum, v);
    }
}

// ---------------------------------------------------------------------------
// Kernel 3: finalize losses
// ---------------------------------------------------------------------------
__global__ void fin_kernel(float* __restrict__ out) {
    double M = g_sqsum / MEAN_DEN;           // mean((zq - zc)^2)
    out[LOSS_OFF + 0] = (float)(1.25 * M);   // loss
    out[LOSS_OFF + 1] = (float)(0.25 * M);   // commitment_loss
    out[LOSS_OFF + 2] = (float)M;            // codebook_loss
}

// ---------------------------------------------------------------------------
extern "C" void kernel_launch(void* const* d_in, const int* in_sizes, int n_in,
                              void* d_out, int out_size) {
    const float *z = nullptr, *emb = nullptr, *proj = nullptr;
    for (int i = 0; i < n_in; i++) {
        if (in_sizes[i] == ZQ_ELEMS)      z    = (const float*)d_in[i];
        else if (in_sizes[i] == NE*CC)    emb  = (const float*)d_in[i];
        else if (in_sizes[i] == CC*CC)    proj = (const float*)d_in[i];
    }
    float* out = (float*)d_out;

    const int SMEM_BYTES = (CC*CB_STRIDE + CC*ZD_STRIDE + CPG + 32) * (int)sizeof(float); // 201,344
    cudaFuncSetAttribute(main_kernel,
                         cudaFuncAttributeMaxDynamicSharedMemorySize, SMEM_BYTES);

    prep_kernel<<<256, 256>>>(emb, proj);
    main_kernel<<<dim3(16, 8), 512, SMEM_BYTES>>>(z, out);
    fin_kernel<<<1, 1>>>(out);
}

// round 7
// speedup vs baseline: 1.7764x; 1.7764x over previous
#include <cuda_runtime.h>

typedef unsigned int u32;

#define CC 256
#define NE 1024
#define CPG 128
#define ZQ_ELEMS (32*256*32*32)
#define LOSS_OFF ZQ_ELEMS
#define IDX_OFF  (ZQ_ELEMS + 3)
#define MEAN_DEN ((double)ZQ_ELEMS)

#define SSTR 260          // smem row stride (floats): 4·row+k covers all banks
#define SCREEN_T 2.5e-3f  // rigorous tf32 screen slack (see analysis)
#define MAXC 12

__device__ __align__(16) float g_codebook[NE*CC];
__device__ float  g_cnorm[NE];
__device__ double g_sqsum;

// m16n8k8 tf32 MMA (Ampere-class PTX; valid on sm_103 family target)
__device__ __forceinline__ void mma_tf32(float* d, u32 a0, u32 a1, u32 a2, u32 a3,
                                         u32 b0, u32 b1) {
    asm volatile(
        "mma.sync.aligned.m16n8k8.row.col.f32.tf32.tf32.f32 "
        "{%0,%1,%2,%3}, {%4,%5,%6,%7}, {%8,%9}, {%0,%1,%2,%3};"
        : "+f"(d[0]), "+f"(d[1]), "+f"(d[2]), "+f"(d[3])
        : "r"(a0), "r"(a1), "r"(a2), "r"(a3), "r"(b0), "r"(b1));
}

// ---------------------------------------------------------------------------
// Kernel 1: codebook = emb @ proj^T (sequential ascending-k fmaf chain per
// element — bit-exact requirement), code norms, zero loss.
// 128 blocks x 256 threads, 8 rows/block; es transposed for LDS.128 broadcast.
// ---------------------------------------------------------------------------
__global__ __launch_bounds__(256)
void prep_kernel(const float* __restrict__ emb,
                 const float* __restrict__ proj) {
    __shared__ __align__(16) float es_t[CC*8];   // [k][j]
    __shared__ float part[8][9];
    int tid  = threadIdx.x;
    int lane = tid & 31;
    int warp = tid >> 5;
    int j0   = blockIdx.x * 8;

    for (int i = tid; i < 8*CC; i += 256) {
        int j = i >> 8, k = i & 255;
        es_t[k*8 + j] = emb[j0*CC + i];
    }
    __syncthreads();

    int i = tid;
    float acc[8];
    #pragma unroll
    for (int j = 0; j < 8; j++) acc[j] = 0.f;

    const float4* pv = (const float4*)(proj + (size_t)i*CC);
    #pragma unroll 4
    for (int k4 = 0; k4 < CC/4; k4++) {
        float4 p = pv[k4];
        #pragma unroll
        for (int s = 0; s < 4; s++) {
            int k = 4*k4 + s;
            float pk = (s == 0) ? p.x : (s == 1) ? p.y : (s == 2) ? p.z : p.w;
            float4 e0 = *(const float4*)(es_t + k*8);
            float4 e1 = *(const float4*)(es_t + k*8 + 4);
            acc[0] = fmaf(e0.x, pk, acc[0]);
            acc[1] = fmaf(e0.y, pk, acc[1]);
            acc[2] = fmaf(e0.z, pk, acc[2]);
            acc[3] = fmaf(e0.w, pk, acc[3]);
            acc[4] = fmaf(e1.x, pk, acc[4]);
            acc[5] = fmaf(e1.y, pk, acc[5]);
            acc[6] = fmaf(e1.z, pk, acc[6]);
            acc[7] = fmaf(e1.w, pk, acc[7]);
        }
    }
    #pragma unroll
    for (int j = 0; j < 8; j++)
        g_codebook[(size_t)(j0 + j)*CC + i] = acc[j];

    #pragma unroll
    for (int j = 0; j < 8; j++) {
        float v = acc[j]*acc[j];
        #pragma unroll
        for (int off = 16; off; off >>= 1)
            v += __shfl_down_sync(0xffffffffu, v, off);
        if (lane == 0) part[j][warp] = v;
    }
    __syncthreads();
    if (tid < 8) {
        float s = 0.f;
        #pragma unroll
        for (int w = 0; w < 8; w++) s += part[tid][w];
        g_cnorm[j0 + tid] = s;
    }
    if (blockIdx.x == 0 && tid == 0) g_sqsum = 0.0;
}

// ---------------------------------------------------------------------------
// Kernel 2: main.  512 blocks (8 groups x 64 chunks) x 256 threads.
// Per block: 64 tokens (16 bh-rows x 4 w) x 128 codes.  tf32 mma.sync screen
// -> candidates within SCREEN_T of screen-min -> exact fp32 sequential-chain
// verify (reference-bit-exact) -> zq/idx/loss from smem.
// ---------------------------------------------------------------------------
extern __shared__ float dsm[];

__global__ __launch_bounds__(256, 1)
void main_kernel(const float* __restrict__ z, float* __restrict__ out) {
    float* Bs = dsm;                  // [128][SSTR] exact fp32 codebook
    float* zs = Bs + 128*SSTR;        // [64][SSTR]  exact fp32 z tokens

    __shared__ float  cn[CPG];
    __shared__ float  znm[64];
    __shared__ float  pmin[2][64];
    __shared__ float  thr_s[64];
    __shared__ int    ccnt[64];
    __shared__ int    cand[64][MAXC];
    __shared__ float  vb[4][64];
    __shared__ int    vi[4][64];
    __shared__ int    sel[64];
    __shared__ double wsum[8];

    int tid  = threadIdx.x;
    int lane = tid & 31;
    int warp = tid >> 5;
    int g     = blockIdx.x >> 6;
    int chunk = blockIdx.x & 63;
    int w0    = g * 4;

    // ---- stage codebook (exact fp32) + cn + z tokens ----
    const float4* cb4 = (const float4*)(g_codebook + (size_t)g*CPG*CC);
    for (int i = tid; i < 8192; i += 256) {
        int j = i >> 6, c4 = i & 63;
        float4 v = cb4[(size_t)j*64 + c4];
        *(float4*)(Bs + j*SSTR + c4*4) = v;
    }
    if (tid < CPG) cn[tid] = g_cnorm[g*CPG + tid];
    if (tid < 64)  ccnt[tid] = 0;

    for (int rr = 0; rr < 2; rr++) {
        int rl = warp + 8*rr;
        int bh = chunk*16 + rl;
        int b = bh >> 5, h = bh & 31;
        const float4* src = (const float4*)(z + (size_t)b*262144 + (size_t)h*32 + w0);
        #pragma unroll
        for (int k = 0; k < 8; k++) {
            int c = lane + 32*k;
            float4 v = src[(size_t)c*256];
            zs[(rl*4+0)*SSTR + c] = v.x;
            zs[(rl*4+1)*SSTR + c] = v.y;
            zs[(rl*4+2)*SSTR + c] = v.z;
            zs[(rl*4+3)*SSTR + c] = v.w;
        }
    }
    __syncthreads();

    // ---- znorm: reference-exact sequential chain (warps 6,7) ----
    if (tid >= 192) {
        int t = tid - 192;
        const float* zr = zs + t*SSTR;
        float a = 0.f;
        #pragma unroll 8
        for (int c = 0; c < CC; c++) {
            float v = zr[c];
            a = __fadd_rn(a, __fmul_rn(v, v));
        }
        znm[t] = a;
    }

    // ---- tf32 screen: warp = (m-tile mw, n-half nh) ----
    int mw  = warp & 3;               // tokens mw*16 .. +15
    int nh  = warp >> 2;              // codes nh*64 .. +63
    int gid = lane >> 2, tg = lane & 3;

    float acc[8][4];
    #pragma unroll
    for (int nt = 0; nt < 8; nt++)
        #pragma unroll
        for (int e = 0; e < 4; e++) acc[nt][e] = 0.f;

    const float* Ab = zs + (mw*16)*SSTR;
    #pragma unroll 2
    for (int kt = 0; kt < 32; kt++) {
        int k0 = kt*8;
        u32 a0 = __float_as_uint(Ab[gid*SSTR + k0 + tg]);
        u32 a1 = __float_as_uint(Ab[(gid+8)*SSTR + k0 + tg]);
        u32 a2 = __float_as_uint(Ab[gid*SSTR + k0 + tg + 4]);
        u32 a3 = __float_as_uint(Ab[(gid+8)*SSTR + k0 + tg + 4]);
        #pragma unroll
        for (int nt = 0; nt < 8; nt++) {
            const float* Bb = Bs + (nh*64 + nt*8 + gid)*SSTR + k0;
            u32 b0 = __float_as_uint(Bb[tg]);
            u32 b1 = __float_as_uint(Bb[tg+4]);
            mma_tf32(acc[nt], a0, a1, a2, a3, b0, b1);
        }
    }

    // ---- screen scores (overwrite acc): s = cn[n] - 2*dot ----
    #pragma unroll
    for (int nt = 0; nt < 8; nt++)
        #pragma unroll
        for (int e = 0; e < 4; e++) {
            int n = nh*64 + nt*8 + 2*tg + (e & 1);
            acc[nt][e] = fmaf(-2.f, acc[nt][e], cn[n]);
        }

    // per-token screen min: token gid (regs e=0,1), token gid+8 (e=2,3)
    float mi0 = 3.4e38f, mi1 = 3.4e38f;
    #pragma unroll
    for (int nt = 0; nt < 8; nt++) {
        mi0 = fminf(mi0, fminf(acc[nt][0], acc[nt][1]));
        mi1 = fminf(mi1, fminf(acc[nt][2], acc[nt][3]));
    }
    mi0 = fminf(mi0, __shfl_xor_sync(0xffffffffu, mi0, 1));
    mi0 = fminf(mi0, __shfl_xor_sync(0xffffffffu, mi0, 2));
    mi1 = fminf(mi1, __shfl_xor_sync(0xffffffffu, mi1, 1));
    mi1 = fminf(mi1, __shfl_xor_sync(0xffffffffu, mi1, 2));
    if (tg == 0) {
        pmin[nh][mw*16 + gid]     = mi0;
        pmin[nh][mw*16 + gid + 8] = mi1;
    }
    __syncthreads();
    if (tid < 64) thr_s[tid] = fminf(pmin[0][tid], pmin[1][tid]) + SCREEN_T;
    __syncthreads();

    // ---- candidate collection (unique (token,code) owner per lane) ----
    #pragma unroll
    for (int nt = 0; nt < 8; nt++)
        #pragma unroll
        for (int e = 0; e < 4; e++) {
            int token = mw*16 + gid + ((e >> 1) ? 8 : 0);
            if (acc[nt][e] <= thr_s[token]) {
                int s = atomicAdd(&ccnt[token], 1);
                if (s < MAXC) cand[token][s] = nh*64 + nt*8 + 2*tg + (e & 1);
            }
        }
    __syncthreads();

    // ---- exact verify (reference-bit-exact), 4 threads per token ----
    {
        int t = tid & 63, q = tid >> 6;
        float best = 3.4e38f;
        int   bj   = 1 << 30;
        float zn = znm[t];
        const float* zr = zs + t*SSTR;
        int nc = ccnt[t];
        if (nc <= MAXC) {
            for (int i = q; i < nc; i += 4) {
                int j = cand[t][i];
                const float* cr = Bs + j*SSTR;
                float a = 0.f;
                #pragma unroll 8
                for (int c = 0; c < CC; c++) a = fmaf(cr[c], zr[c], a);
                float d = __fsub_rn(__fadd_rn(zn, cn[j]), __fadd_rn(a, a));
                if (d < best || (d == best && j < bj)) { best = d; bj = j; }
            }
        } else {
            // overflow fallback: exact scan of all 128 codes
            for (int j = q; j < 128; j += 4) {
                const float* cr = Bs + j*SSTR;
                float a = 0.f;
                #pragma unroll 8
                for (int c = 0; c < CC; c++) a = fmaf(cr[c], zr[c], a);
                float d = __fsub_rn(__fadd_rn(zn, cn[j]), __fadd_rn(a, a));
                if (d < best || (d == best && j < bj)) { best = d; bj = j; }
            }
        }
        vb[q][t] = best; vi[q][t] = bj;
    }
    __syncthreads();
    if (tid < 64) {
        float best = vb[0][tid]; int bj = vi[0][tid];
        #pragma unroll
        for (int q = 1; q < 4; q++) {
            float d = vb[q][tid]; int j = vi[q][tid];
            if (d < best || (d == best && j < bj)) { best = d; bj = j; }
        }
        sel[tid] = bj;
    }
    __syncthreads();

    // ---- epilogue: zq write (float4 strided) + loss from smem ----
    float lsum_f = 0.f;
    for (int rr = 0; rr < 2; rr++) {
        int rl = warp + 8*rr;
        int bh = chunk*16 + rl;
        int b = bh >> 5, h = bh & 31;
        float4* dst = (float4*)(out + (size_t)b*262144 + (size_t)h*32 + w0);
        int s0 = sel[rl*4+0], s1 = sel[rl*4+1], s2 = sel[rl*4+2], s3 = sel[rl*4+3];
        #pragma unroll
        for (int k = 0; k < 8; k++) {
            int c = lane + 32*k;
            float4 v;
            v.x = Bs[s0*SSTR + c];
            v.y = Bs[s1*SSTR + c];
            v.z = Bs[s2*SSTR + c];
            v.w = Bs[s3*SSTR + c];
            dst[(size_t)c*256] = v;
            float d0 = v.x - zs[(rl*4+0)*SSTR + c];
            float d1 = v.y - zs[(rl*4+1)*SSTR + c];
            float d2 = v.z - zs[(rl*4+2)*SSTR + c];
            float d3 = v.w - zs[(rl*4+3)*SSTR + c];
            lsum_f = fmaf(d0, d0, lsum_f);
            lsum_f = fmaf(d1, d1, lsum_f);
            lsum_f = fmaf(d2, d2, lsum_f);
            lsum_f = fmaf(d3, d3, lsum_f);
        }
    }

    // idx output
    if (tid < 64) {
        int rl = tid >> 2, wi = tid & 3;
        int bh = chunk*16 + rl;
        int b = bh >> 5, h = bh & 31;
        out[IDX_OFF + b*1024 + h*32 + w0 + wi] = (float)(g*CPG + sel[tid]);
    }

    // loss reduce, one double atomic per block
    double lsum = (double)lsum_f;
    #pragma unroll
    for (int off = 16; off; off >>= 1)
        lsum += __shfl_down_sync(0xffffffffu, lsum, off);
    if (lane == 0) wsum[warp] = lsum;
    __syncthreads();
    if (warp == 0) {
        double v = (lane < 8) ? wsum[lane] : 0.0;
        #pragma unroll
        for (int off = 4; off; off >>= 1)
            v += __shfl_down_sync(0xffffffffu, v, off);
        if (lane == 0) atomicAdd(&g_sqsum, v);
    }
}

// ---------------------------------------------------------------------------
__global__ void fin_kernel(float* __restrict__ out) {
    double M = g_sqsum / MEAN_DEN;
    out[LOSS_OFF + 0] = (float)(1.25 * M);
    out[LOSS_OFF + 1] = (float)(0.25 * M);
    out[LOSS_OFF + 2] = (float)M;
}

// ---------------------------------------------------------------------------
extern "C" void kernel_launch(void* const* d_in, const int* in_sizes, int n_in,
                              void* d_out, int out_size) {
    const float *z = nullptr, *emb = nullptr, *proj = nullptr;
    for (int i = 0; i < n_in; i++) {
        if (in_sizes[i] == ZQ_ELEMS)      z    = (const float*)d_in[i];
        else if (in_sizes[i] == NE*CC)    emb  = (const float*)d_in[i];
        else if (in_sizes[i] == CC*CC)    proj = (const float*)d_in[i];
    }
    float* out = (float*)d_out;

    const int SMEM_BYTES = (128*SSTR + 64*SSTR) * (int)sizeof(float);  // 199,680
    cudaFuncSetAttribute(main_kernel,
                         cudaFuncAttributeMaxDynamicSharedMemorySize, SMEM_BYTES);

    prep_kernel<<<128, 256>>>(emb, proj);
    main_kernel<<<512, 256, SMEM_BYTES>>>(z, out);
    fin_kernel<<<1, 1>>>(out);
}